// round 2
// baseline (speedup 1.0000x reference)
#include <cuda_runtime.h>
#include <cuda_bf16.h>
#include <cstdint>

#define N_NODES 100000
#define N_FEAT  512
#define HIDDEN  128
#define N_CLASS 16
#define N_EDGES 3200000
#define ALPHA   0.25f

// ---------------- device scratch (no allocations allowed) ----------------
__device__ float g_local[N_NODES * N_CLASS];   // local_logits
__device__ float g_tmp[N_NODES * N_CLASS];     // intermediate logits
__device__ int   g_cnt[N_NODES];               // out-degree histogram
__device__ int   g_rowptr[N_NODES + 1];        // CSR row pointers (by src)
__device__ int   g_fill[N_NODES];              // scatter cursors
__device__ float g_scale[N_NODES];             // (1-alpha)/max(deg,1e-12)
__device__ int   g_csr[N_EDGES];               // CSR column indices (dst)

// ---------------- helpers ----------------
__device__ __forceinline__ uint32_t f2tf(float f) {
    uint32_t u;
    asm("cvt.rna.tf32.f32 %0, %1;" : "=r"(u) : "f"(f));
    return u;
}

__device__ __forceinline__ void mma_tf32(float* d,
                                         uint32_t a0, uint32_t a1, uint32_t a2, uint32_t a3,
                                         uint32_t b0, uint32_t b1) {
    asm volatile(
        "mma.sync.aligned.m16n8k8.row.col.f32.tf32.tf32.f32 "
        "{%0,%1,%2,%3},{%4,%5,%6,%7},{%8,%9},{%0,%1,%2,%3};\n"
        : "+f"(d[0]), "+f"(d[1]), "+f"(d[2]), "+f"(d[3])
        : "r"(a0), "r"(a1), "r"(a2), "r"(a3), "r"(b0), "r"(b1));
}

// ---------------- CSR build ----------------
__global__ void k_zero_cnt() {
    int i = blockIdx.x * blockDim.x + threadIdx.x;
    if (i < N_NODES) g_cnt[i] = 0;
}

__global__ void k_hist(const int* __restrict__ esrc) {
    int e = blockIdx.x * blockDim.x + threadIdx.x;
    if (e < N_EDGES) atomicAdd(&g_cnt[esrc[e]], 1);
}

// single-block exclusive scan of g_cnt -> g_rowptr (+ fill cursors + scale)
__global__ void k_scan() {
    __shared__ int wsums[32];
    int tid  = threadIdx.x;
    int lane = tid & 31;
    int wid  = tid >> 5;
    int total = 0;
    for (int base = 0; base < N_NODES; base += 1024) {
        int i = base + tid;
        int v = (i < N_NODES) ? g_cnt[i] : 0;
        int x = v;
        #pragma unroll
        for (int d = 1; d < 32; d <<= 1) {
            int y = __shfl_up_sync(0xffffffffu, x, d);
            if (lane >= d) x += y;
        }
        if (lane == 31) wsums[wid] = x;
        __syncthreads();
        if (wid == 0) {
            int w = wsums[lane];
            int xs = w;
            #pragma unroll
            for (int d = 1; d < 32; d <<= 1) {
                int y = __shfl_up_sync(0xffffffffu, xs, d);
                if (lane >= d) xs += y;
            }
            wsums[lane] = xs;
        }
        __syncthreads();
        int warp_prefix = (wid > 0) ? wsums[wid - 1] : 0;
        int excl = x - v + warp_prefix;
        if (i < N_NODES) {
            int rp = total + excl;
            g_rowptr[i] = rp;
            g_fill[i]   = rp;
            g_scale[i]  = (1.0f - ALPHA) / fmaxf((float)v, 1e-12f);
        }
        int block_sum = wsums[31];
        __syncthreads();
        total += block_sum;
    }
    if (tid == 0) g_rowptr[N_NODES] = total;
}

__global__ void k_scatter(const int* __restrict__ esrc, const int* __restrict__ edst) {
    int e = blockIdx.x * blockDim.x + threadIdx.x;
    if (e < N_EDGES) {
        int p = atomicAdd(&g_fill[esrc[e]], 1);
        g_csr[p] = edst[e];
    }
}

// ---------------- fused GEMM: local = relu(x@W1) @ W2 ----------------
// BM=64 rows/block, full HIDDEN=128 cols, BK=32. 256 threads = 8 warps (4m x 2n),
// warp tile 16x64 via m16n8k8 tf32 mma. Second GEMM (x@W2) from smem with FFMA.
#define GBM 64
#define GBK 32
#define AS_STRIDE 36   // % 32 == 4 -> conflict-free fragment loads
#define BS_STRIDE 136  // % 32 == 8 -> conflict-free fragment loads
#define HID_STRIDE 129 // % 32 == 1 -> conflict-free row reads in 2nd gemm

__global__ __launch_bounds__(256) void k_gemm(const float* __restrict__ x,
                                              const float* __restrict__ W1,
                                              const float* __restrict__ W2) {
    // union: [As|Bs] during mainloop, hid afterwards
    __shared__ __align__(16) unsigned char smem_raw[GBM * HID_STRIDE * 4]; // 33024 B
    __shared__ float W2s[HIDDEN * N_CLASS]; // 8 KB
    __shared__ float outS[GBM * N_CLASS];   // 4 KB
    uint32_t* As = (uint32_t*)smem_raw;                        // [64][36]
    uint32_t* Bs = (uint32_t*)(smem_raw + GBM * AS_STRIDE * 4); // [32][136]
    float*    hid = (float*)smem_raw;                          // [64][129]

    int tid  = threadIdx.x;
    int lane = tid & 31;
    int warp = tid >> 5;
    int blockRow = blockIdx.x * GBM;

    for (int i = tid; i < HIDDEN * N_CLASS; i += 256) W2s[i] = W2[i];

    int warpM = warp >> 1;   // 0..3
    int warpN = warp & 1;    // 0..1
    int grp = lane >> 2;     // 0..7
    int tig = lane & 3;      // 0..3

    float acc[8][4];
    #pragma unroll
    for (int nt = 0; nt < 8; nt++)
        #pragma unroll
        for (int r = 0; r < 4; r++) acc[nt][r] = 0.0f;

    for (int k0 = 0; k0 < N_FEAT; k0 += GBK) {
        // load A tile 64x32 (2 float4/thread)
        #pragma unroll
        for (int it = 0; it < 2; it++) {
            int idx = tid + it * 256;          // 0..511
            int r   = idx >> 3;                // 8 float4 per row
            int c4  = idx & 7;
            float4 v = make_float4(0.f, 0.f, 0.f, 0.f);
            int gr = blockRow + r;
            if (gr < N_NODES) v = *(const float4*)&x[gr * N_FEAT + k0 + c4 * 4];
            int base = r * AS_STRIDE + c4 * 4;
            As[base + 0] = f2tf(v.x); As[base + 1] = f2tf(v.y);
            As[base + 2] = f2tf(v.z); As[base + 3] = f2tf(v.w);
        }
        // load B tile 32x128 (4 float4/thread)
        #pragma unroll
        for (int it = 0; it < 4; it++) {
            int idx = tid + it * 256;          // 0..1023
            int r   = idx >> 5;                // 32 float4 per row
            int c4  = idx & 31;
            float4 v = *(const float4*)&W1[(k0 + r) * HIDDEN + c4 * 4];
            int base = r * BS_STRIDE + c4 * 4;
            Bs[base + 0] = f2tf(v.x); Bs[base + 1] = f2tf(v.y);
            Bs[base + 2] = f2tf(v.z); Bs[base + 3] = f2tf(v.w);
        }
        __syncthreads();
        #pragma unroll
        for (int ks = 0; ks < 4; ks++) {
            int kk = ks * 8;
            uint32_t a0 = As[(warpM * 16 + grp) * AS_STRIDE + kk + tig];
            uint32_t a1 = As[(warpM * 16 + grp + 8) * AS_STRIDE + kk + tig];
            uint32_t a2 = As[(warpM * 16 + grp) * AS_STRIDE + kk + tig + 4];
            uint32_t a3 = As[(warpM * 16 + grp + 8) * AS_STRIDE + kk + tig + 4];
            #pragma unroll
            for (int nt = 0; nt < 8; nt++) {
                int col = warpN * 64 + nt * 8 + grp;
                uint32_t b0 = Bs[(kk + tig) * BS_STRIDE + col];
                uint32_t b1 = Bs[(kk + tig + 4) * BS_STRIDE + col];
                mma_tf32(acc[nt], a0, a1, a2, a3, b0, b1);
            }
        }
        __syncthreads();
    }

    // relu -> hid (smem)
    {
        int r0 = warpM * 16 + grp;
        int r1 = r0 + 8;
        #pragma unroll
        for (int nt = 0; nt < 8; nt++) {
            int c = warpN * 64 + nt * 8 + tig * 2;
            hid[r0 * HID_STRIDE + c]     = fmaxf(acc[nt][0], 0.f);
            hid[r0 * HID_STRIDE + c + 1] = fmaxf(acc[nt][1], 0.f);
            hid[r1 * HID_STRIDE + c]     = fmaxf(acc[nt][2], 0.f);
            hid[r1 * HID_STRIDE + c + 1] = fmaxf(acc[nt][3], 0.f);
        }
    }
    __syncthreads();

    // second gemm: out[64][16] = hid[64][128] @ W2[128][16]
    int r = tid & 63;
    int q = tid >> 6;   // 0..3, each handles 32 of the 128 h-dims
    float o[N_CLASS];
    #pragma unroll
    for (int c = 0; c < N_CLASS; c++) o[c] = 0.f;
    int h0 = q * 32;
    for (int h = h0; h < h0 + 32; h++) {
        float v = hid[r * HID_STRIDE + h];
        #pragma unroll
        for (int c = 0; c < N_CLASS; c++) o[c] += v * W2s[h * N_CLASS + c];
    }
    if (q == 0) {
        #pragma unroll
        for (int c = 0; c < N_CLASS; c++) outS[r * N_CLASS + c] = o[c];
    }
    __syncthreads();
    if (q == 1) {
        #pragma unroll
        for (int c = 0; c < N_CLASS; c++) outS[r * N_CLASS + c] += o[c];
    }
    __syncthreads();
    if (q == 2) {
        #pragma unroll
        for (int c = 0; c < N_CLASS; c++) outS[r * N_CLASS + c] += o[c];
    }
    __syncthreads();
    if (q == 3) {
        int gr = blockRow + r;
        if (gr < N_NODES) {
            #pragma unroll
            for (int j = 0; j < 4; j++) {
                float4 v;
                v.x = outS[r * N_CLASS + j * 4 + 0] + o[j * 4 + 0];
                v.y = outS[r * N_CLASS + j * 4 + 1] + o[j * 4 + 1];
                v.z = outS[r * N_CLASS + j * 4 + 2] + o[j * 4 + 2];
                v.w = outS[r * N_CLASS + j * 4 + 3] + o[j * 4 + 3];
                *(float4*)&g_local[gr * N_CLASS + j * 4] = v;
            }
        }
    }
}

// ---------------- SpMM: half-warp (16 lanes = 16 classes) per node ----------------
__global__ void k_spmm1() {  // in = g_local, out = g_tmp
    int t = blockIdx.x * blockDim.x + threadIdx.x;
    int node = t >> 4;
    int c = t & 15;
    if (node >= N_NODES) return;
    int s = g_rowptr[node], e = g_rowptr[node + 1];
    float a0 = 0.f, a1 = 0.f;
    int i = s;
    for (; i + 2 <= e; i += 2) {
        int j0 = g_csr[i], j1 = g_csr[i + 1];
        a0 += g_local[j0 * N_CLASS + c];
        a1 += g_local[j1 * N_CLASS + c];
    }
    if (i < e) a0 += g_local[g_csr[i] * N_CLASS + c];
    g_tmp[node * N_CLASS + c] =
        g_scale[node] * (a0 + a1) + ALPHA * g_local[node * N_CLASS + c];
}

__global__ void k_spmm2_softmax(float* __restrict__ out) {  // in = g_tmp -> log_softmax
    int t = blockIdx.x * blockDim.x + threadIdx.x;
    int node = t >> 4;
    int c = t & 15;
    if (node >= N_NODES) return;
    int s = g_rowptr[node], e = g_rowptr[node + 1];
    float a0 = 0.f, a1 = 0.f;
    int i = s;
    for (; i + 2 <= e; i += 2) {
        int j0 = g_csr[i], j1 = g_csr[i + 1];
        a0 += g_tmp[j0 * N_CLASS + c];
        a1 += g_tmp[j1 * N_CLASS + c];
    }
    if (i < e) a0 += g_tmp[g_csr[i] * N_CLASS + c];
    float v = g_scale[node] * (a0 + a1) + ALPHA * g_local[node * N_CLASS + c];

    // log_softmax over the 16-lane group
    float m = v;
    #pragma unroll
    for (int k = 8; k >= 1; k >>= 1) m = fmaxf(m, __shfl_xor_sync(0xffffffffu, m, k));
    float ex = __expf(v - m);
    float ss = ex;
    #pragma unroll
    for (int k = 8; k >= 1; k >>= 1) ss += __shfl_xor_sync(0xffffffffu, ss, k);
    out[node * N_CLASS + c] = v - m - __logf(ss);
}

// ---------------- launch ----------------
extern "C" void kernel_launch(void* const* d_in, const int* in_sizes, int n_in,
                              void* d_out, int out_size) {
    const float* x    = (const float*)d_in[0];
    const float* W1   = (const float*)d_in[1];
    const float* W2   = (const float*)d_in[2];
    const int*   esrc = (const int*)d_in[3];
    const int*   edst = (const int*)d_in[4];
    float* out = (float*)d_out;

    k_zero_cnt<<<(N_NODES + 255) / 256, 256>>>();
    k_hist<<<(N_EDGES + 255) / 256, 256>>>(esrc);
    k_scan<<<1, 1024>>>();
    k_scatter<<<(N_EDGES + 255) / 256, 256>>>(esrc, edst);
    k_gemm<<<(N_NODES + GBM - 1) / GBM, 256>>>(x, W1, W2);
    k_spmm1<<<(N_NODES * N_CLASS + 255) / 256, 256>>>();
    k_spmm2_softmax<<<(N_NODES * N_CLASS + 255) / 256, 256>>>(out);
}

// round 7
// speedup vs baseline: 1.5698x; 1.5698x over previous
#include <cuda_runtime.h>
#include <cuda_bf16.h>
#include <cstdint>

#define N_NODES 100000
#define N_FEAT  512
#define HIDDEN  128
#define N_CLASS 16
#define N_EDGES 3200000
#define ALPHA   0.25f

#define NCHUNK 98   // ceil(100000/1024)

// ---------------- device scratch ----------------
__device__ float g_local[N_NODES * N_CLASS];
__device__ float g_tmp[N_NODES * N_CLASS];
__device__ int   g_cnt[N_NODES];
__device__ int   g_rowptr[N_NODES + 1];
__device__ int   g_fill[N_NODES];
__device__ float g_scale[N_NODES];
__device__ int   g_csr[N_EDGES];
__device__ int   g_chunksum[NCHUNK];
__device__ int   g_chunkoff[NCHUNK];
__device__ uint32_t g_W1t[N_FEAT * HIDDEN];   // W1 pre-converted to tf32 (rna)

// ---------------- helpers ----------------
__device__ __forceinline__ uint32_t f2tf(float f) {
    uint32_t u;
    asm("cvt.rna.tf32.f32 %0, %1;" : "=r"(u) : "f"(f));
    return u;
}

__device__ __forceinline__ void mma_tf32(float* d,
                                         uint32_t a0, uint32_t a1, uint32_t a2, uint32_t a3,
                                         uint32_t b0, uint32_t b1) {
    asm volatile(
        "mma.sync.aligned.m16n8k8.row.col.f32.tf32.tf32.f32 "
        "{%0,%1,%2,%3},{%4,%5,%6,%7},{%8,%9},{%0,%1,%2,%3};\n"
        : "+f"(d[0]), "+f"(d[1]), "+f"(d[2]), "+f"(d[3])
        : "r"(a0), "r"(a1), "r"(a2), "r"(a3), "r"(b0), "r"(b1));
}

__device__ __forceinline__ void cp16(uint32_t dst, const void* src) {
    asm volatile("cp.async.cg.shared.global [%0], [%1], 16;\n"
                 :: "r"(dst), "l"(src) : "memory");
}
#define CP_COMMIT asm volatile("cp.async.commit_group;\n" ::: "memory")
#define CP_WAIT(N) asm volatile("cp.async.wait_group %0;\n" :: "n"(N) : "memory")

// ---------------- W1 pre-conversion (rna) ----------------
__global__ void k_cvt_w1(const float* __restrict__ W1) {
    int i = blockIdx.x * blockDim.x + threadIdx.x;
    if (i < N_FEAT * HIDDEN) g_W1t[i] = f2tf(W1[i]);
}

// ---------------- CSR build ----------------
__global__ void k_zero_cnt() {
    int i = blockIdx.x * blockDim.x + threadIdx.x;
    if (i < N_NODES) g_cnt[i] = 0;
}

__global__ void k_hist(const int* __restrict__ esrc) {
    int t = blockIdx.x * blockDim.x + threadIdx.x;
    if (t < N_EDGES / 4) {
        int4 s = ((const int4*)esrc)[t];
        atomicAdd(&g_cnt[s.x], 1);
        atomicAdd(&g_cnt[s.y], 1);
        atomicAdd(&g_cnt[s.z], 1);
        atomicAdd(&g_cnt[s.w], 1);
    }
}

// scan phase 1: per-1024-chunk sums
__global__ void k_scan1() {
    __shared__ int ws[32];
    int tid = threadIdx.x, lane = tid & 31, wid = tid >> 5;
    int i = blockIdx.x * 1024 + tid;
    int v = (i < N_NODES) ? g_cnt[i] : 0;
    #pragma unroll
    for (int d = 16; d >= 1; d >>= 1) v += __shfl_xor_sync(0xffffffffu, v, d);
    if (lane == 0) ws[wid] = v;
    __syncthreads();
    if (wid == 0) {
        int s = ws[lane];
        #pragma unroll
        for (int d = 16; d >= 1; d >>= 1) s += __shfl_xor_sync(0xffffffffu, s, d);
        if (lane == 0) g_chunksum[blockIdx.x] = s;
    }
}

// scan phase 2: exclusive scan of chunk sums (1 block, 128 threads)
__global__ void k_scan2() {
    __shared__ int ws[4];
    int tid = threadIdx.x, lane = tid & 31, wid = tid >> 5;
    int v = (tid < NCHUNK) ? g_chunksum[tid] : 0;
    int x = v;
    #pragma unroll
    for (int d = 1; d < 32; d <<= 1) {
        int y = __shfl_up_sync(0xffffffffu, x, d);
        if (lane >= d) x += y;
    }
    if (lane == 31) ws[wid] = x;
    __syncthreads();
    if (tid == 0) {
        int s = 0;
        #pragma unroll
        for (int w = 0; w < 4; w++) { int t = ws[w]; ws[w] = s; s += t; }
    }
    __syncthreads();
    int excl = x - v + ws[wid];
    if (tid < NCHUNK) g_chunkoff[tid] = excl;
    if (tid == NCHUNK - 1) g_rowptr[N_NODES] = excl + v;
}

// scan phase 3: in-chunk exclusive scan + offset; writes rowptr/fill/scale
__global__ void k_scan3() {
    __shared__ int ws[32];
    int tid = threadIdx.x, lane = tid & 31, wid = tid >> 5;
    int i = blockIdx.x * 1024 + tid;
    int v = (i < N_NODES) ? g_cnt[i] : 0;
    int x = v;
    #pragma unroll
    for (int d = 1; d < 32; d <<= 1) {
        int y = __shfl_up_sync(0xffffffffu, x, d);
        if (lane >= d) x += y;
    }
    if (lane == 31) ws[wid] = x;
    __syncthreads();
    if (wid == 0) {
        int w = ws[lane];
        int xs = w;
        #pragma unroll
        for (int d = 1; d < 32; d <<= 1) {
            int y = __shfl_up_sync(0xffffffffu, xs, d);
            if (lane >= d) xs += y;
        }
        ws[lane] = xs;
    }
    __syncthreads();
    int warp_prefix = (wid > 0) ? ws[wid - 1] : 0;
    int excl = x - v + warp_prefix + g_chunkoff[blockIdx.x];
    if (i < N_NODES) {
        g_rowptr[i] = excl;
        g_fill[i]   = excl;
        g_scale[i]  = (1.0f - ALPHA) / fmaxf((float)v, 1e-12f);
    }
}

__global__ void k_scatter(const int* __restrict__ esrc, const int* __restrict__ edst) {
    int t = blockIdx.x * blockDim.x + threadIdx.x;
    if (t < N_EDGES / 4) {
        int4 s = ((const int4*)esrc)[t];
        int4 d = ((const int4*)edst)[t];
        int p;
        p = atomicAdd(&g_fill[s.x], 1); g_csr[p] = d.x;
        p = atomicAdd(&g_fill[s.y], 1); g_csr[p] = d.y;
        p = atomicAdd(&g_fill[s.z], 1); g_csr[p] = d.z;
        p = atomicAdd(&g_fill[s.w], 1); g_csr[p] = d.w;
    }
}

// ---------------- fused GEMM: local = relu(x@W1) @ W2 ----------------
// BM=128, BN=128(=HIDDEN), BK=32, 256 thr = 8 warps (4m x 2n), warp tile 32x64.
// 2-stage cp.async double buffering. A fragments cvt.rna'd in registers;
// B (=W1) pre-converted to tf32-rna in g_W1t.
#define GBM 128
#define GBK 32
#define ASTR 36
#define BSTR 136
#define A_BYTES (GBM * ASTR * 4)            // 18432
#define B_BYTES (GBK * BSTR * 4)            // 17408
#define STAGE_BYTES (A_BYTES + B_BYTES)     // 35840
#define W2_OFF (2 * STAGE_BYTES)            // 71680
#define OUTS_OFF (W2_OFF + HIDDEN * N_CLASS * 4)  // 79872
#define OUTSTR 17
#define GEMM_SMEM (OUTS_OFF + GBM * OUTSTR * 4)   // 88576
#define HIDSTR 129

__global__ __launch_bounds__(256, 2) void k_gemm(const float* __restrict__ x,
                                                 const float* __restrict__ W2) {
    extern __shared__ __align__(16) char sm[];
    float* W2s  = (float*)(sm + W2_OFF);
    float* outS = (float*)(sm + OUTS_OFF);
    float* hid  = (float*)sm;
    uint32_t smem_u32 = (uint32_t)__cvta_generic_to_shared(sm);

    int tid  = threadIdx.x;
    int lane = tid & 31;
    int warp = tid >> 5;
    int blockRow = blockIdx.x * GBM;

    int warpM = warp >> 1;   // 0..3
    int warpN = warp & 1;    // 0..1
    int grp = lane >> 2;     // 0..7
    int tig = lane & 3;      // 0..3

    for (int i = tid; i < HIDDEN * N_CLASS; i += 256) W2s[i] = W2[i];

    float acc[2][8][4];
    #pragma unroll
    for (int mt = 0; mt < 2; mt++)
        #pragma unroll
        for (int nt = 0; nt < 8; nt++)
            #pragma unroll
            for (int r = 0; r < 4; r++) acc[mt][nt][r] = 0.0f;

    // tile loader
    auto load_tiles = [&](int kiter, int st) {
        int k0 = kiter * GBK;
        uint32_t abase = smem_u32 + st * STAGE_BYTES;
        uint32_t bbase = abase + A_BYTES;
        #pragma unroll
        for (int it = 0; it < 4; it++) {
            int idx = tid + it * 256;
            int r = idx >> 3, c4 = idx & 7;
            int gr = blockRow + r;
            if (gr >= N_NODES) gr = N_NODES - 1;
            cp16(abase + (r * ASTR + c4 * 4) * 4,
                 &x[(size_t)gr * N_FEAT + k0 + c4 * 4]);
        }
        #pragma unroll
        for (int it = 0; it < 4; it++) {
            int idx = tid + it * 256;
            int r = idx >> 5, c4 = idx & 31;
            cp16(bbase + (r * BSTR + c4 * 4) * 4,
                 &g_W1t[(k0 + r) * HIDDEN + c4 * 4]);
        }
    };

    auto compute = [&](int st) {
        const uint32_t* As = (const uint32_t*)(sm + st * STAGE_BYTES);
        const uint32_t* Bs = (const uint32_t*)(sm + st * STAGE_BYTES + A_BYTES);
        #pragma unroll
        for (int ks = 0; ks < 4; ks++) {
            int kk = ks * 8;
            uint32_t a[2][4];
            #pragma unroll
            for (int mt = 0; mt < 2; mt++) {
                int r0 = warpM * 32 + mt * 16 + grp;
                a[mt][0] = f2tf(__uint_as_float(As[r0 * ASTR + kk + tig]));
                a[mt][1] = f2tf(__uint_as_float(As[(r0 + 8) * ASTR + kk + tig]));
                a[mt][2] = f2tf(__uint_as_float(As[r0 * ASTR + kk + tig + 4]));
                a[mt][3] = f2tf(__uint_as_float(As[(r0 + 8) * ASTR + kk + tig + 4]));
            }
            #pragma unroll
            for (int nt = 0; nt < 8; nt++) {
                int col = warpN * 64 + nt * 8 + grp;
                uint32_t b0 = Bs[(kk + tig) * BSTR + col];
                uint32_t b1 = Bs[(kk + tig + 4) * BSTR + col];
                mma_tf32(acc[0][nt], a[0][0], a[0][1], a[0][2], a[0][3], b0, b1);
                mma_tf32(acc[1][nt], a[1][0], a[1][1], a[1][2], a[1][3], b0, b1);
            }
        }
    };

    load_tiles(0, 0);
    CP_COMMIT;
    #pragma unroll 1
    for (int i = 0; i < N_FEAT / GBK; i++) {
        int st = i & 1;
        if (i + 1 < N_FEAT / GBK) {
            load_tiles(i + 1, st ^ 1);
            CP_COMMIT;
            CP_WAIT(1);
        } else {
            CP_WAIT(0);
        }
        __syncthreads();
        compute(st);
        __syncthreads();
    }

    // relu -> hid (reuses stage smem; mainloop fully synced above)
    #pragma unroll
    for (int mt = 0; mt < 2; mt++) {
        int r0 = warpM * 32 + mt * 16 + grp;
        #pragma unroll
        for (int nt = 0; nt < 8; nt++) {
            int c = warpN * 64 + nt * 8 + tig * 2;
            hid[r0 * HIDSTR + c]           = fmaxf(acc[mt][nt][0], 0.f);
            hid[r0 * HIDSTR + c + 1]       = fmaxf(acc[mt][nt][1], 0.f);
            hid[(r0 + 8) * HIDSTR + c]     = fmaxf(acc[mt][nt][2], 0.f);
            hid[(r0 + 8) * HIDSTR + c + 1] = fmaxf(acc[mt][nt][3], 0.f);
        }
    }
    __syncthreads();

    // second gemm: out[128][16] = hid[128][128] @ W2[128][16], 2-way h split
    int r = tid & 127;
    int q = tid >> 7;  // 0..1
    float o[N_CLASS];
    #pragma unroll
    for (int c = 0; c < N_CLASS; c++) o[c] = 0.f;
    int h0 = q * 64;
    #pragma unroll 4
    for (int h = h0; h < h0 + 64; h++) {
        float v = hid[r * HIDSTR + h];
        #pragma unroll
        for (int c = 0; c < N_CLASS; c++) o[c] += v * W2s[h * N_CLASS + c];
    }
    if (q == 0) {
        #pragma unroll
        for (int c = 0; c < N_CLASS; c++) outS[r * OUTSTR + c] = o[c];
    }
    __syncthreads();
    if (q == 1) {
        int gr = blockRow + r;
        if (gr < N_NODES) {
            #pragma unroll
            for (int j = 0; j < 4; j++) {
                float4 v;
                v.x = outS[r * OUTSTR + j * 4 + 0] + o[j * 4 + 0];
                v.y = outS[r * OUTSTR + j * 4 + 1] + o[j * 4 + 1];
                v.z = outS[r * OUTSTR + j * 4 + 2] + o[j * 4 + 2];
                v.w = outS[r * OUTSTR + j * 4 + 3] + o[j * 4 + 3];
                *(float4*)&g_local[gr * N_CLASS + j * 4] = v;
            }
        }
    }
}

// ---------------- SpMM: 16 lanes = 16 classes per node, shuffle-broadcast idx ----------------
// PHASE 0: read g_local -> write g_tmp. PHASE 1: read g_tmp -> log_softmax -> out.
// Tables are selected INSIDE device code (never pass __device__ symbols from host!).
template<int PHASE>
__global__ void k_spmm_t(float* __restrict__ outfinal) {
    const float* tbl = (PHASE == 0) ? g_local : g_tmp;
    int t = blockIdx.x * blockDim.x + threadIdx.x;
    int node = t >> 4;
    if (node >= N_NODES) return;
    int l16 = threadIdx.x & 15;
    unsigned mask = 0xFFFFu << (threadIdx.x & 16);

    int s = g_rowptr[node], e = g_rowptr[node + 1];
    float a = 0.f;
    int i = s;
    for (; i + 16 <= e; i += 16) {
        int idx = __ldg(&g_csr[i + l16]);
        #pragma unroll
        for (int q = 0; q < 16; q++) {
            int j = __shfl_sync(mask, idx, q, 16);
            a += __ldg(&tbl[j * N_CLASS + l16]);
        }
    }
    int rem = e - i;
    if (rem) {
        int idx = (l16 < rem) ? __ldg(&g_csr[i + l16]) : 0;
        for (int q = 0; q < rem; q++) {
            int j = __shfl_sync(mask, idx, q, 16);
            a += __ldg(&tbl[j * N_CLASS + l16]);
        }
    }
    float v = g_scale[node] * a + ALPHA * g_local[node * N_CLASS + l16];

    if (PHASE == 0) {
        g_tmp[node * N_CLASS + l16] = v;
    } else {
        float m = v;
        #pragma unroll
        for (int k = 8; k >= 1; k >>= 1) m = fmaxf(m, __shfl_xor_sync(mask, m, k, 16));
        float ex = __expf(v - m);
        float ss = ex;
        #pragma unroll
        for (int k = 8; k >= 1; k >>= 1) ss += __shfl_xor_sync(mask, ss, k, 16);
        outfinal[node * N_CLASS + l16] = v - m - __logf(ss);
    }
}

// ---------------- launch ----------------
extern "C" void kernel_launch(void* const* d_in, const int* in_sizes, int n_in,
                              void* d_out, int out_size) {
    const float* x    = (const float*)d_in[0];
    const float* W1   = (const float*)d_in[1];
    const float* W2   = (const float*)d_in[2];
    const int*   esrc = (const int*)d_in[3];
    const int*   edst = (const int*)d_in[4];
    float* out = (float*)d_out;

    cudaFuncSetAttribute(k_gemm, cudaFuncAttributeMaxDynamicSharedMemorySize, GEMM_SMEM);

    k_cvt_w1<<<(N_FEAT * HIDDEN + 255) / 256, 256>>>(W1);
    k_zero_cnt<<<(N_NODES + 255) / 256, 256>>>();
    k_hist<<<(N_EDGES / 4 + 255) / 256, 256>>>(esrc);
    k_scan1<<<NCHUNK, 1024>>>();
    k_scan2<<<1, 128>>>();
    k_scan3<<<NCHUNK, 1024>>>();
    k_scatter<<<(N_EDGES / 4 + 255) / 256, 256>>>(esrc, edst);
    k_gemm<<<(N_NODES + GBM - 1) / GBM, 256, GEMM_SMEM>>>(x, W2);
    k_spmm_t<0><<<(N_NODES * N_CLASS + 255) / 256, 256>>>(nullptr);
    k_spmm_t<1><<<(N_NODES * N_CLASS + 255) / 256, 256>>>(out);
}

// round 8
// speedup vs baseline: 1.7863x; 1.1379x over previous
#include <cuda_runtime.h>
#include <cuda_bf16.h>
#include <cstdint>

#define N_NODES 100000
#define N_FEAT  512
#define HIDDEN  128
#define N_CLASS 16
#define N_EDGES 3200000
#define ALPHA   0.25f

#define NCHUNK 98   // ceil(100000/1024)

// ---------------- device scratch ----------------
__device__ float g_local[N_NODES * N_CLASS];
__device__ float g_tmp[N_NODES * N_CLASS];
__device__ int   g_cnt[N_NODES];
__device__ int   g_rowptr[N_NODES + 1];
__device__ int   g_fill[N_NODES];
__device__ float g_scale[N_NODES];
__device__ int   g_csr[N_EDGES];
__device__ int   g_chunksum[NCHUNK];
__device__ int   g_chunkoff[NCHUNK];
__device__ uint32_t g_W1t[N_FEAT * HIDDEN];   // W1 pre-converted to tf32 (rna)

// ---------------- helpers ----------------
__device__ __forceinline__ uint32_t f2tf(float f) {
    uint32_t u;
    asm("cvt.rna.tf32.f32 %0, %1;" : "=r"(u) : "f"(f));
    return u;
}

__device__ __forceinline__ void mma_tf32(float* d,
                                         uint32_t a0, uint32_t a1, uint32_t a2, uint32_t a3,
                                         uint32_t b0, uint32_t b1) {
    asm volatile(
        "mma.sync.aligned.m16n8k8.row.col.f32.tf32.tf32.f32 "
        "{%0,%1,%2,%3},{%4,%5,%6,%7},{%8,%9},{%0,%1,%2,%3};\n"
        : "+f"(d[0]), "+f"(d[1]), "+f"(d[2]), "+f"(d[3])
        : "r"(a0), "r"(a1), "r"(a2), "r"(a3), "r"(b0), "r"(b1));
}

__device__ __forceinline__ void cp16(uint32_t dst, const void* src) {
    asm volatile("cp.async.cg.shared.global [%0], [%1], 16;\n"
                 :: "r"(dst), "l"(src) : "memory");
}
#define CP_COMMIT asm volatile("cp.async.commit_group;\n" ::: "memory")
#define CP_WAIT(N) asm volatile("cp.async.wait_group %0;\n" :: "n"(N) : "memory")

// ---------------- W1 pre-conversion (rna) ----------------
__global__ void k_cvt_w1(const float* __restrict__ W1) {
    int i = blockIdx.x * blockDim.x + threadIdx.x;
    if (i < N_FEAT * HIDDEN) g_W1t[i] = f2tf(W1[i]);
}

// ---------------- CSR build ----------------
__global__ void k_zero_cnt() {
    int i = blockIdx.x * blockDim.x + threadIdx.x;
    if (i < N_NODES) g_cnt[i] = 0;
}

__global__ void k_hist(const int* __restrict__ esrc) {
    int t = blockIdx.x * blockDim.x + threadIdx.x;
    if (t < N_EDGES / 4) {
        int4 s = ((const int4*)esrc)[t];
        atomicAdd(&g_cnt[s.x], 1);
        atomicAdd(&g_cnt[s.y], 1);
        atomicAdd(&g_cnt[s.z], 1);
        atomicAdd(&g_cnt[s.w], 1);
    }
}

// scan phase 1: per-1024-chunk sums
__global__ void k_scan1() {
    __shared__ int ws[32];
    int tid = threadIdx.x, lane = tid & 31, wid = tid >> 5;
    int i = blockIdx.x * 1024 + tid;
    int v = (i < N_NODES) ? g_cnt[i] : 0;
    #pragma unroll
    for (int d = 16; d >= 1; d >>= 1) v += __shfl_xor_sync(0xffffffffu, v, d);
    if (lane == 0) ws[wid] = v;
    __syncthreads();
    if (wid == 0) {
        int s = ws[lane];
        #pragma unroll
        for (int d = 16; d >= 1; d >>= 1) s += __shfl_xor_sync(0xffffffffu, s, d);
        if (lane == 0) g_chunksum[blockIdx.x] = s;
    }
}

// scan phase 2: exclusive scan of chunk sums (1 block, 128 threads)
__global__ void k_scan2() {
    __shared__ int ws[4];
    int tid = threadIdx.x, lane = tid & 31, wid = tid >> 5;
    int v = (tid < NCHUNK) ? g_chunksum[tid] : 0;
    int x = v;
    #pragma unroll
    for (int d = 1; d < 32; d <<= 1) {
        int y = __shfl_up_sync(0xffffffffu, x, d);
        if (lane >= d) x += y;
    }
    if (lane == 31) ws[wid] = x;
    __syncthreads();
    if (tid == 0) {
        int s = 0;
        #pragma unroll
        for (int w = 0; w < 4; w++) { int t = ws[w]; ws[w] = s; s += t; }
    }
    __syncthreads();
    int excl = x - v + ws[wid];
    if (tid < NCHUNK) g_chunkoff[tid] = excl;
    if (tid == NCHUNK - 1) g_rowptr[N_NODES] = excl + v;
}

// scan phase 3: in-chunk exclusive scan + offset; writes rowptr/fill/scale
__global__ void k_scan3() {
    __shared__ int ws[32];
    int tid = threadIdx.x, lane = tid & 31, wid = tid >> 5;
    int i = blockIdx.x * 1024 + tid;
    int v = (i < N_NODES) ? g_cnt[i] : 0;
    int x = v;
    #pragma unroll
    for (int d = 1; d < 32; d <<= 1) {
        int y = __shfl_up_sync(0xffffffffu, x, d);
        if (lane >= d) x += y;
    }
    if (lane == 31) ws[wid] = x;
    __syncthreads();
    if (wid == 0) {
        int w = ws[lane];
        int xs = w;
        #pragma unroll
        for (int d = 1; d < 32; d <<= 1) {
            int y = __shfl_up_sync(0xffffffffu, xs, d);
            if (lane >= d) xs += y;
        }
        ws[lane] = xs;
    }
    __syncthreads();
    int warp_prefix = (wid > 0) ? ws[wid - 1] : 0;
    int excl = x - v + warp_prefix + g_chunkoff[blockIdx.x];
    if (i < N_NODES) {
        g_rowptr[i] = excl;
        g_fill[i]   = excl;
        g_scale[i]  = (1.0f - ALPHA) / fmaxf((float)v, 1e-12f);
    }
}

__global__ void k_scatter(const int* __restrict__ esrc, const int* __restrict__ edst) {
    int t = blockIdx.x * blockDim.x + threadIdx.x;
    if (t < N_EDGES / 4) {
        int4 s = ((const int4*)esrc)[t];
        int4 d = ((const int4*)edst)[t];
        int p;
        p = atomicAdd(&g_fill[s.x], 1); g_csr[p] = d.x;
        p = atomicAdd(&g_fill[s.y], 1); g_csr[p] = d.y;
        p = atomicAdd(&g_fill[s.z], 1); g_csr[p] = d.z;
        p = atomicAdd(&g_fill[s.w], 1); g_csr[p] = d.w;
    }
}

// ---------------- fused GEMM: local = relu(x@W1) @ W2 ----------------
#define GBM 128
#define GBK 32
#define ASTR 36
#define BSTR 136
#define A_BYTES (GBM * ASTR * 4)            // 18432
#define B_BYTES (GBK * BSTR * 4)            // 17408
#define STAGE_BYTES (A_BYTES + B_BYTES)     // 35840
#define W2_OFF (2 * STAGE_BYTES)            // 71680
#define OUTS_OFF (W2_OFF + HIDDEN * N_CLASS * 4)  // 79872
#define OUTSTR 17
#define GEMM_SMEM (OUTS_OFF + GBM * OUTSTR * 4)   // 88576
#define HIDSTR 129

__global__ __launch_bounds__(256, 2) void k_gemm(const float* __restrict__ x,
                                                 const float* __restrict__ W2) {
    extern __shared__ __align__(16) char sm[];
    float* W2s  = (float*)(sm + W2_OFF);
    float* outS = (float*)(sm + OUTS_OFF);
    float* hid  = (float*)sm;
    uint32_t smem_u32 = (uint32_t)__cvta_generic_to_shared(sm);

    int tid  = threadIdx.x;
    int lane = tid & 31;
    int warp = tid >> 5;
    int blockRow = blockIdx.x * GBM;

    int warpM = warp >> 1;   // 0..3
    int warpN = warp & 1;    // 0..1
    int grp = lane >> 2;     // 0..7
    int tig = lane & 3;      // 0..3

    for (int i = tid; i < HIDDEN * N_CLASS; i += 256) W2s[i] = W2[i];

    float acc[2][8][4];
    #pragma unroll
    for (int mt = 0; mt < 2; mt++)
        #pragma unroll
        for (int nt = 0; nt < 8; nt++)
            #pragma unroll
            for (int r = 0; r < 4; r++) acc[mt][nt][r] = 0.0f;

    auto load_tiles = [&](int kiter, int st) {
        int k0 = kiter * GBK;
        uint32_t abase = smem_u32 + st * STAGE_BYTES;
        uint32_t bbase = abase + A_BYTES;
        #pragma unroll
        for (int it = 0; it < 4; it++) {
            int idx = tid + it * 256;
            int r = idx >> 3, c4 = idx & 7;
            int gr = blockRow + r;
            if (gr >= N_NODES) gr = N_NODES - 1;
            cp16(abase + (r * ASTR + c4 * 4) * 4,
                 &x[(size_t)gr * N_FEAT + k0 + c4 * 4]);
        }
        #pragma unroll
        for (int it = 0; it < 4; it++) {
            int idx = tid + it * 256;
            int r = idx >> 5, c4 = idx & 31;
            cp16(bbase + (r * BSTR + c4 * 4) * 4,
                 &g_W1t[(k0 + r) * HIDDEN + c4 * 4]);
        }
    };

    auto compute = [&](int st) {
        const uint32_t* As = (const uint32_t*)(sm + st * STAGE_BYTES);
        const uint32_t* Bs = (const uint32_t*)(sm + st * STAGE_BYTES + A_BYTES);
        #pragma unroll
        for (int ks = 0; ks < 4; ks++) {
            int kk = ks * 8;
            uint32_t a[2][4];
            #pragma unroll
            for (int mt = 0; mt < 2; mt++) {
                int r0 = warpM * 32 + mt * 16 + grp;
                a[mt][0] = f2tf(__uint_as_float(As[r0 * ASTR + kk + tig]));
                a[mt][1] = f2tf(__uint_as_float(As[(r0 + 8) * ASTR + kk + tig]));
                a[mt][2] = f2tf(__uint_as_float(As[r0 * ASTR + kk + tig + 4]));
                a[mt][3] = f2tf(__uint_as_float(As[(r0 + 8) * ASTR + kk + tig + 4]));
            }
            #pragma unroll
            for (int nt = 0; nt < 8; nt++) {
                int col = warpN * 64 + nt * 8 + grp;
                uint32_t b0 = Bs[(kk + tig) * BSTR + col];
                uint32_t b1 = Bs[(kk + tig + 4) * BSTR + col];
                mma_tf32(acc[0][nt], a[0][0], a[0][1], a[0][2], a[0][3], b0, b1);
                mma_tf32(acc[1][nt], a[1][0], a[1][1], a[1][2], a[1][3], b0, b1);
            }
        }
    };

    load_tiles(0, 0);
    CP_COMMIT;
    #pragma unroll 1
    for (int i = 0; i < N_FEAT / GBK; i++) {
        int st = i & 1;
        if (i + 1 < N_FEAT / GBK) {
            load_tiles(i + 1, st ^ 1);
            CP_COMMIT;
            CP_WAIT(1);
        } else {
            CP_WAIT(0);
        }
        __syncthreads();
        compute(st);
        __syncthreads();
    }

    // relu -> hid
    #pragma unroll
    for (int mt = 0; mt < 2; mt++) {
        int r0 = warpM * 32 + mt * 16 + grp;
        #pragma unroll
        for (int nt = 0; nt < 8; nt++) {
            int c = warpN * 64 + nt * 8 + tig * 2;
            hid[r0 * HIDSTR + c]           = fmaxf(acc[mt][nt][0], 0.f);
            hid[r0 * HIDSTR + c + 1]       = fmaxf(acc[mt][nt][1], 0.f);
            hid[(r0 + 8) * HIDSTR + c]     = fmaxf(acc[mt][nt][2], 0.f);
            hid[(r0 + 8) * HIDSTR + c + 1] = fmaxf(acc[mt][nt][3], 0.f);
        }
    }
    __syncthreads();

    // second gemm: out[128][16] = hid[128][128] @ W2[128][16], 2-way h split
    int r = tid & 127;
    int q = tid >> 7;  // 0..1
    float o[N_CLASS];
    #pragma unroll
    for (int c = 0; c < N_CLASS; c++) o[c] = 0.f;
    int h0 = q * 64;
    #pragma unroll 4
    for (int h = h0; h < h0 + 64; h++) {
        float v = hid[r * HIDSTR + h];
        #pragma unroll
        for (int c = 0; c < N_CLASS; c++) o[c] += v * W2s[h * N_CLASS + c];
    }
    if (q == 0) {
        #pragma unroll
        for (int c = 0; c < N_CLASS; c++) outS[r * OUTSTR + c] = o[c];
    }
    __syncthreads();
    if (q == 1) {
        int gr = blockRow + r;
        if (gr < N_NODES) {
            #pragma unroll
            for (int j = 0; j < 4; j++) {
                float4 v;
                v.x = outS[r * OUTSTR + j * 4 + 0] + o[j * 4 + 0];
                v.y = outS[r * OUTSTR + j * 4 + 1] + o[j * 4 + 1];
                v.z = outS[r * OUTSTR + j * 4 + 2] + o[j * 4 + 2];
                v.w = outS[r * OUTSTR + j * 4 + 3] + o[j * 4 + 3];
                *(float4*)&g_local[gr * N_CLASS + j * 4] = v;
            }
        }
    }
}

// ---------------- SpMM: 16 lanes = 16 classes per node, shuffle-broadcast idx ----------------
template<int PHASE>
__global__ void k_spmm_t(float* __restrict__ outfinal) {
    const float* tbl = (PHASE == 0) ? g_local : g_tmp;
    int t = blockIdx.x * blockDim.x + threadIdx.x;
    int node = t >> 4;
    if (node >= N_NODES) return;
    int l16 = threadIdx.x & 15;
    unsigned mask = 0xFFFFu << (threadIdx.x & 16);

    int s = g_rowptr[node], e = g_rowptr[node + 1];
    float a = 0.f;
    int i = s;
    for (; i + 16 <= e; i += 16) {
        int idx = __ldg(&g_csr[i + l16]);
        #pragma unroll
        for (int q = 0; q < 16; q++) {
            int j = __shfl_sync(mask, idx, q, 16);
            a += __ldg(&tbl[j * N_CLASS + l16]);
        }
    }
    int rem = e - i;
    if (rem) {
        int idx = (l16 < rem) ? __ldg(&g_csr[i + l16]) : 0;
        for (int q = 0; q < rem; q++) {
            int j = __shfl_sync(mask, idx, q, 16);
            a += __ldg(&tbl[j * N_CLASS + l16]);
        }
    }
    float v = g_scale[node] * a + ALPHA * g_local[node * N_CLASS + l16];

    if (PHASE == 0) {
        g_tmp[node * N_CLASS + l16] = v;
    } else {
        float m = v;
        #pragma unroll
        for (int k = 8; k >= 1; k >>= 1) m = fmaxf(m, __shfl_xor_sync(mask, m, k, 16));
        float ex = __expf(v - m);
        float ss = ex;
        #pragma unroll
        for (int k = 8; k >= 1; k >>= 1) ss += __shfl_xor_sync(mask, ss, k, 16);
        outfinal[node * N_CLASS + l16] = v - m - __logf(ss);
    }
}

// ---------------- launch: fork CSR chain onto side stream, join before SpMM ----------------
extern "C" void kernel_launch(void* const* d_in, const int* in_sizes, int n_in,
                              void* d_out, int out_size) {
    const float* x    = (const float*)d_in[0];
    const float* W1   = (const float*)d_in[1];
    const float* W2   = (const float*)d_in[2];
    const int*   esrc = (const int*)d_in[3];
    const int*   edst = (const int*)d_in[4];
    float* out = (float*)d_out;

    // one-time resource setup on the first (uncaptured correctness) call;
    // the captured call performs identical launches every time.
    static cudaStream_t s2 = nullptr;
    static cudaEvent_t evFork = nullptr, evJoin = nullptr;
    if (s2 == nullptr) {
        cudaStreamCreateWithFlags(&s2, cudaStreamNonBlocking);
        cudaEventCreateWithFlags(&evFork, cudaEventDisableTiming);
        cudaEventCreateWithFlags(&evJoin, cudaEventDisableTiming);
        cudaFuncSetAttribute(k_gemm, cudaFuncAttributeMaxDynamicSharedMemorySize, GEMM_SMEM);
    }

    // fork
    cudaEventRecord(evFork, 0);
    cudaStreamWaitEvent(s2, evFork, 0);

    // chain A: CSR build (side stream) — L2/atomic-bound, complements GEMM
    k_zero_cnt<<<(N_NODES + 255) / 256, 256, 0, s2>>>();
    k_hist<<<(N_EDGES / 4 + 255) / 256, 256, 0, s2>>>(esrc);
    k_scan1<<<NCHUNK, 1024, 0, s2>>>();
    k_scan2<<<1, 128, 0, s2>>>();
    k_scan3<<<NCHUNK, 1024, 0, s2>>>();
    k_scatter<<<(N_EDGES / 4 + 255) / 256, 256, 0, s2>>>(esrc, edst);
    cudaEventRecord(evJoin, s2);

    // chain B: features (main stream) — tensor/smem-bound
    k_cvt_w1<<<(N_FEAT * HIDDEN + 255) / 256, 256>>>(W1);
    k_gemm<<<(N_NODES + GBM - 1) / GBM, 256, GEMM_SMEM>>>(x, W2);

    // join, then propagation
    cudaStreamWaitEvent(0, evJoin, 0);
    k_spmm_t<0><<<(N_NODES * N_CLASS + 255) / 256, 256>>>(nullptr);
    k_spmm_t<1><<<(N_NODES * N_CLASS + 255) / 256, 256>>>(out);
}